// round 2
// baseline (speedup 1.0000x reference)
#include <cuda_runtime.h>
#include <cuda_bf16.h>

#define NPTS  1024
#define CAP   256
#define R2    (0.15f * 0.15f)

// 10 distinct nonzero rotation diagonals, ordered so FFMA2 pairs are
// (0,1)(2,3)(4,5)(6,7)(8,9):
// rots 0-3: full-sign diagonals (multiplicity 1 each);
// rots 4-9: single-axis diagonals (multiplicity 2 each);
// remaining 8 of the 24 rotations have zero diagonal -> closed-form c2.
__constant__ float c_SX[10] = {1.f, 1.f,-1.f,-1.f,  1.f,-1.f, 0.f, 0.f, 0.f, 0.f};
__constant__ float c_SY[10] = {1.f,-1.f, 1.f,-1.f,  0.f, 0.f, 1.f,-1.f, 0.f, 0.f};
__constant__ float c_SZ[10] = {1.f,-1.f,-1.f, 1.f,  0.f, 0.f, 0.f, 0.f, 1.f,-1.f};

__device__ __forceinline__ unsigned long long pack2(float a, float b) {
    unsigned long long r;
    asm("mov.b64 %0, {%1, %2};" : "=l"(r) : "r"(__float_as_uint(a)), "r"(__float_as_uint(b)));
    return r;
}
__device__ __forceinline__ void unpack2(unsigned long long v, float& lo, float& hi) {
    asm("mov.b64 {%0, %1}, %2;" : "=f"(lo), "=f"(hi) : "l"(v));
}
__device__ __forceinline__ unsigned long long ffma2(unsigned long long a,
                                                    unsigned long long b,
                                                    unsigned long long c) {
    unsigned long long d;
    asm("fma.rn.f32x2 %0, %1, %2, %3;" : "=l"(d) : "l"(a), "l"(b), "l"(c));
    return d;
}

__global__ __launch_bounds__(64)
void pe_kernel(const float* __restrict__ x, const float* __restrict__ W1,
               const float* __restrict__ b1, const float* __restrict__ W2,
               const float* __restrict__ b2, float* __restrict__ out)
{
    __shared__ float sy[NPTS * 3];                // this batch's points (12 KB)
    __shared__ float sg[CAP * 3];                 // in-ball relative coords
    __shared__ float sd2[CAP];
    __shared__ float ssel[63 * 3];                // overflow-selected 63 nearest
    __shared__ __align__(16) float sh1p[5 * 64];  // h1 pairs: [pair p][c][parity]
    __shared__ float sw1[96];
    __shared__ float sb1[32];
    __shared__ int   scnt, sselcnt;

    const int tid  = threadIdx.x;                 // = output channel o (0..63)
    const int warp = tid >> 5;                    // = rotation parity it produces
    const int lane = tid & 31;
    const int b    = blockIdx.x >> 10;
    const int n    = blockIdx.x & (NPTS - 1);
    const float* xb = x + b * NPTS * 3;

    for (int i = tid; i < NPTS * 3; i += 64) sy[i] = xb[i];
    for (int i = tid; i < 96; i += 64)       sw1[i] = W1[i];   // (R1 bug: was single pass)
    if (tid < 32) sb1[tid] = b1[tid];
    if (tid == 0) { scnt = 0; sselcnt = 0; }
    __syncthreads();

    const float qx = sy[n * 3 + 0], qy = sy[n * 3 + 1], qz = sy[n * 3 + 2];

    // ---- ball query: gather in-ball neighbors (excluding self) ----
    for (int j = tid; j < NPTS; j += 64) {
        float dx = sy[j * 3 + 0] - qx;
        float dy = sy[j * 3 + 1] - qy;
        float dz = sy[j * 3 + 2] - qz;
        float d2 = dx * dx + dy * dy + dz * dz;
        if (d2 <= R2 && j != n) {
            int p = atomicAdd(&scnt, 1);
            if (p < CAP) {
                sg[p * 3 + 0] = dx; sg[p * 3 + 1] = dy; sg[p * 3 + 2] = dz;
                sd2[p] = d2;
            }
        }
    }
    __syncthreads();

    int cnt = min(scnt, CAP);
    const float* glist = sg;
    int m = cnt;

    // Overflow (>63 others in ball): exact rank-select the 63 nearest.
    // Statistically unreachable for uniform points; kept for top_k parity
    // (self, d2=0, always occupies one of the 64 slots).
    if (cnt > 63) {
        for (int e = tid; e < cnt; e += 64) {
            float de = sd2[e];
            int rank = 0;
            for (int f = 0; f < cnt; ++f) {
                float df = sd2[f];
                rank += (df < de) || (df == de && f < e);
            }
            if (rank < 63) {
                int p = atomicAdd(&sselcnt, 1);
                ssel[p * 3 + 0] = sg[e * 3 + 0];
                ssel[p * 3 + 1] = sg[e * 3 + 1];
                ssel[p * 3 + 2] = sg[e * 3 + 2];
            }
        }
        __syncthreads();
        glist = ssel;
        m = 63;
    }

    // ---- per-thread: W2 row packed (w,w) for f32x2 math ----
    unsigned long long wpk[32];
    const float b2o = __ldg(&b2[tid]);
    float acc_self = 0.f;          // bias-free layer-2 response to gp = 0
    #pragma unroll
    for (int c = 0; c < 32; ++c) {
        float w = __ldg(&W2[tid * 32 + c]);
        wpk[c] = pack2(w, w);
        acc_self = fmaf(w, fmaxf(sb1[c], 0.f), acc_self);
    }

    // Running max of bias-free pre-activations per rotation. relu/bias are
    // monotone -> applied once at the end. Self/padding slot seeds the max.
    float mv[10];
    #pragma unroll
    for (int r = 0; r < 10; ++r) mv[r] = acc_self;

    // ---- main loop over real neighbors ----
    for (int k = 0; k < m; ++k) {
        const float gx = glist[k * 3 + 0];
        const float gy = glist[k * 3 + 1];
        const float gz = glist[k * 3 + 2];

        // layer 1 (cooperative): warp w computes rotations of parity w.
        #pragma unroll
        for (int i = 0; i < 5; ++i) {
            const int rot = 2 * i + warp;      // uniform within each warp
            float vx = c_SX[rot] * gx;
            float vy = c_SY[rot] * gy;
            float vz = c_SZ[rot] * gz;
            float a = fmaf(sw1[lane * 3 + 0], vx,
                      fmaf(sw1[lane * 3 + 1], vy,
                      fmaf(sw1[lane * 3 + 2], vz, sb1[lane])));
            sh1p[i * 64 + lane * 2 + warp] = fmaxf(a, 0.f);
        }
        __syncthreads();

        // layer 2: 5 independent f32x2 chains (rotation pairs) per thread.
        #pragma unroll
        for (int p = 0; p < 5; ++p) {
            const ulonglong2* hp =
                reinterpret_cast<const ulonglong2*>(&sh1p[p * 64]);
            unsigned long long acc = 0ull;   // (+0.f, +0.f)
            #pragma unroll
            for (int q = 0; q < 16; ++q) {
                ulonglong2 v = hp[q];        // pairs for channels 2q, 2q+1
                acc = ffma2(v.x, wpk[2 * q + 0], acc);
                acc = ffma2(v.y, wpk[2 * q + 1], acc);
            }
            float lo, hi;
            unpack2(acc, lo, hi);
            mv[2 * p + 0] = fmaxf(mv[2 * p + 0], lo);
            mv[2 * p + 1] = fmaxf(mv[2 * p + 1], hi);
        }
        __syncthreads();
    }

    // mean over 24 rotations: 4 full (w=1) + 6 axis (w=2) + 8 zero-diag (c2)
    const float c2 = fmaxf(acc_self + b2o, 0.f);
    float fs = 8.f * c2;
    #pragma unroll
    for (int r = 0; r < 4; ++r)  fs += fmaxf(mv[r] + b2o, 0.f);
    #pragma unroll
    for (int r = 4; r < 10; ++r) fs += 2.f * fmaxf(mv[r] + b2o, 0.f);

    out[(b * 64 + tid) * NPTS + n] = fs * (1.f / 24.f);
}

extern "C" void kernel_launch(void* const* d_in, const int* in_sizes, int n_in,
                              void* d_out, int out_size)
{
    const float* x  = (const float*)d_in[0];  // [B,1024,3]
    const float* W1 = (const float*)d_in[1];  // [32,3]
    const float* b1 = (const float*)d_in[2];  // [32]
    const float* W2 = (const float*)d_in[3];  // [64,32]
    const float* b2 = (const float*)d_in[4];  // [64]
    float* out = (float*)d_out;               // [B,64,1024]

    int total_pts = in_sizes[0] / 3;          // B * 1024
    pe_kernel<<<total_pts, 64>>>(x, W1, b1, W2, b2, out);
}

// round 7
// speedup vs baseline: 1.2513x; 1.2513x over previous
#include <cuda_runtime.h>
#include <cuda_bf16.h>

#define NPTS  1024
#define CAP   192
#define R2    (0.15f * 0.15f)

__device__ __forceinline__ unsigned long long ffma2(unsigned long long a,
                                                    unsigned long long b,
                                                    unsigned long long c) {
    unsigned long long d;
    asm("fma.rn.f32x2 %0, %1, %2, %3;" : "=l"(d) : "l"(a), "l"(b), "l"(c));
    return d;
}
__device__ __forceinline__ void unpack2(unsigned long long v, float& lo, float& hi) {
    asm("mov.b64 {%0, %1}, %2;" : "=f"(lo), "=f"(hi) : "l"(v));
}

__global__ __launch_bounds__(64)
void pe_kernel(const float* __restrict__ x, const float* __restrict__ W1,
               const float* __restrict__ b1, const float* __restrict__ W2,
               const float* __restrict__ b2, float* __restrict__ out)
{
    __shared__ float sg[CAP * 3];                 // in-ball relative coords
    __shared__ float sd2[CAP];
    __shared__ float ssel[63 * 3];                // overflow-selected 63 nearest
    // per-warp double-buffered layer-1 tile: [warp][buf][rot*32 + channel]
    __shared__ __align__(16) float sh1[2][2][320];
    __shared__ int scnt, sselcnt;

    const int tid  = threadIdx.x;                 // = output channel o (0..63)
    const int wrp  = tid >> 5;
    const int c    = tid & 31;                    // lane = layer-1 channel
    const int b    = blockIdx.x >> 10;
    const int n    = blockIdx.x & (NPTS - 1);
    const float* xb = x + b * NPTS * 3;

    if (tid == 0) { scnt = 0; sselcnt = 0; }
    __syncthreads();

    const float qx = __ldg(&xb[n * 3 + 0]);
    const float qy = __ldg(&xb[n * 3 + 1]);
    const float qz = __ldg(&xb[n * 3 + 2]);

    // ---- ball query: scan all points straight from global (L1/L2 hit) ----
    for (int j = tid; j < NPTS; j += 64) {
        float dx = __ldg(&xb[j * 3 + 0]) - qx;
        float dy = __ldg(&xb[j * 3 + 1]) - qy;
        float dz = __ldg(&xb[j * 3 + 2]) - qz;
        float d2 = dx * dx + dy * dy + dz * dz;
        if (d2 <= R2 && j != n) {
            int p = atomicAdd(&scnt, 1);
            if (p < CAP) {
                sg[p * 3 + 0] = dx; sg[p * 3 + 1] = dy; sg[p * 3 + 2] = dz;
                sd2[p] = d2;
            }
        }
    }
    __syncthreads();

    int cnt = min(scnt, CAP);
    const float* glist = sg;
    int m = cnt;

    // Overflow (>63 others in ball): exact rank-select 63 nearest
    // (top_k parity; statistically unreachable for uniform points).
    if (cnt > 63) {
        for (int e = tid; e < cnt; e += 64) {
            float de = sd2[e];
            int rank = 0;
            for (int f = 0; f < cnt; ++f) {
                float df = sd2[f];
                rank += (df < de) || (df == de && f < e);
            }
            if (rank < 63) {
                int p = atomicAdd(&sselcnt, 1);
                ssel[p * 3 + 0] = sg[e * 3 + 0];
                ssel[p * 3 + 1] = sg[e * 3 + 1];
                ssel[p * 3 + 2] = sg[e * 3 + 2];
            }
        }
        __syncthreads();
        glist = ssel;
        m = 63;
    }

    // ---- per-lane layer-1 weights (registers) ----
    const float w1x = __ldg(&W1[c * 3 + 0]);
    const float w1y = __ldg(&W1[c * 3 + 1]);
    const float w1z = __ldg(&W1[c * 3 + 2]);
    const float b1c = __ldg(&b1[c]);

    // ---- W2 row: natural channel-adjacent packing, no duplication ----
    const unsigned long long* w2row =
        reinterpret_cast<const unsigned long long*>(W2 + tid * 32);
    unsigned long long wpk[16];
    const float b2o = __ldg(&b2[tid]);
    float acc_self = 0.f;                 // bias-free response to gp = 0
    #pragma unroll
    for (int q = 0; q < 16; ++q) {
        wpk[q] = __ldg(&w2row[q]);
        float lo, hi; unpack2(wpk[q], lo, hi);
        acc_self = fmaf(lo, fmaxf(__ldg(&b1[2 * q + 0]), 0.f), acc_self);
        acc_self = fmaf(hi, fmaxf(__ldg(&b1[2 * q + 1]), 0.f), acc_self);
    }

    float mv[10];
    #pragma unroll
    for (int r = 0; r < 10; ++r) mv[r] = acc_self;

    float* buf0 = &sh1[wrp][0][0];
    float* buf1 = &sh1[wrp][1][0];

    // ---- main loop: no block barriers; one __syncwarp per neighbor ----
    for (int k = 0; k < m; ++k) {
        float* buf = (k & 1) ? buf1 : buf0;
        const float gx = glist[k * 3 + 0];
        const float gy = glist[k * 3 + 1];
        const float gz = glist[k * 3 + 2];

        // layer 1, all 10 rots for this lane's channel via diagonal algebra:
        // rot0..3 = b +/-px +/-py +/-pz (dets +); rot4..9 = b +/- single axis.
        float px = w1x * gx, py = w1y * gy, pz = w1z * gz;
        float a_ = b1c + px, d_ = b1c - px;
        float u  = py + pz,  v  = py - pz;
        buf[0 * 32 + c] = fmaxf(a_ + u, 0.f);
        buf[1 * 32 + c] = fmaxf(a_ - u, 0.f);
        buf[2 * 32 + c] = fmaxf(d_ + v, 0.f);
        buf[3 * 32 + c] = fmaxf(d_ - v, 0.f);
        buf[4 * 32 + c] = fmaxf(a_, 0.f);
        buf[5 * 32 + c] = fmaxf(d_, 0.f);
        buf[6 * 32 + c] = fmaxf(b1c + py, 0.f);
        buf[7 * 32 + c] = fmaxf(b1c - py, 0.f);
        buf[8 * 32 + c] = fmaxf(b1c + pz, 0.f);
        buf[9 * 32 + c] = fmaxf(b1c - pz, 0.f);
        __syncwarp();

        // layer 2: 10 independent f32x2 chains; accumulator lanes =
        // (even-channel partial, odd-channel partial) of one rotation.
        #pragma unroll
        for (int r = 0; r < 10; ++r) {
            const ulonglong2* hp =
                reinterpret_cast<const ulonglong2*>(buf + r * 32);
            unsigned long long acc = 0ull;
            #pragma unroll
            for (int q = 0; q < 8; ++q) {
                ulonglong2 hv = hp[q];           // channels 4q..4q+3, rot r
                acc = ffma2(hv.x, wpk[2 * q + 0], acc);
                acc = ffma2(hv.y, wpk[2 * q + 1], acc);
            }
            float lo, hi; unpack2(acc, lo, hi);
            mv[r] = fmaxf(mv[r], lo + hi);
        }
    }

    // mean over 24 rotations: 4 full (w=1) + 6 axis (w=2) + 8 zero-diag (c2)
    const float c2 = fmaxf(acc_self + b2o, 0.f);
    float fs = 8.f * c2;
    #pragma unroll
    for (int r = 0; r < 4; ++r)  fs += fmaxf(mv[r] + b2o, 0.f);
    #pragma unroll
    for (int r = 4; r < 10; ++r) fs += 2.f * fmaxf(mv[r] + b2o, 0.f);

    out[(b * 64 + tid) * NPTS + n] = fs * (1.f / 24.f);
}

extern "C" void kernel_launch(void* const* d_in, const int* in_sizes, int n_in,
                              void* d_out, int out_size)
{
    const float* x  = (const float*)d_in[0];  // [B,1024,3]
    const float* W1 = (const float*)d_in[1];  // [32,3]
    const float* b1 = (const float*)d_in[2];  // [32]
    const float* W2 = (const float*)d_in[3];  // [64,32]
    const float* b2 = (const float*)d_in[4];  // [64]
    float* out = (float*)d_out;               // [B,64,1024]

    int total_pts = in_sizes[0] / 3;          // B * 1024
    pe_kernel<<<total_pts, 64>>>(x, W1, b1, W2, b2, out);
}